// round 6
// baseline (speedup 1.0000x reference)
#include <cuda_runtime.h>
#include <cuda_bf16.h>

#define R_ROWS 4              // output rows per warp-strip
#define NROWS  (R_ROWS + 2)   // pixel rows streamed (with vertical halo)
#define WPB    4              // warps per block

// KAN 3x3 conv, shared KANLinear(9->1), cubic B-spline on uniform grid.
// Warp-per-strip register-rolling design (R=4 for occupancy):
//  - lane l owns output columns (2l, 2l+1); warp covers the full 64-wide row.
//  - pixel rows stream downward; per pixel compute 9 per-feature values
//    v[f] = silu(x)*bw[f] + P_{f,cell(x)}(u) and accumulate directly into
//    3 rolling row-accumulators (rows r-1, r, r+1) per column.
//  - horizontal neighbor exchange via 6 warp shuffles per pixel row.
//  - padding pixels are x=0: silu=0, spline value Z[f] (cell j=5, u=0.5);
//    lane-edge shuffles are patched with Z, out-of-image rows use x=0.
//  - 4 warps/block share one poly-table build.
__global__ __launch_bounds__(128, 7)
void kan_conv_kernel(const float* __restrict__ x,
                     const float* __restrict__ bw,
                     const float* __restrict__ sw,
                     const float* __restrict__ ss,
                     float* __restrict__ out)
{
    __shared__ float4 poly[12 * 9];   // [cell j][feature f]; row j=11 is all zeros

    const int lane  = threadIdx.x & 31;
    const int warp  = threadIdx.x >> 5;
    const int img   = blockIdx.x >> 2;                    // 1024 blocks = 256 images x 4
    const int strip = ((blockIdx.x & 3) << 2) | warp;     // 0..15
    const int y0    = strip * R_ROWS;

    // ---- build polynomial table once per block ----
    // Uniform cubic B-spline bases contracted with padded weights W[c]:
    //   a0=(W0+4W1+W2)/6, a1=(W2-W0)/2, a2=(W0-2W1+W2)/2, a3=(W3-W0+3(W1-W2))/6
    if (threadIdx.x < 108) {
        int t = threadIdx.x;
        int j = t / 9, f = t - j * 9;
        float4 v = make_float4(0.f, 0.f, 0.f, 0.f);
        if (j < 11) {
            float scale = __ldg(&ss[f]);
            float W[4];
            #pragma unroll
            for (int c = 0; c < 4; c++) {
                int bi = j + c - 3;
                W[c] = (bi >= 0 && bi < 8) ? __ldg(&sw[f * 8 + bi]) * scale : 0.f;
            }
            const float S = 1.f / 6.f;
            v.x = (W[0] + 4.f * W[1] + W[2]) * S;
            v.y = (W[2] - W[0]) * 0.5f;
            v.z = (W[0] - 2.f * W[1] + W[2]) * 0.5f;
            v.w = (W[3] - W[0] + 3.f * (W[1] - W[2])) * S;
        }
        poly[t] = v;
    }
    float bwr[9];
    #pragma unroll
    for (int f = 0; f < 9; f++) bwr[f] = __ldg(&bw[f]);
    __syncthreads();

    // ---- spline value at x = 0 (padding pixels): cell j=5, u=0.5, silu=0 ----
    float Z[9];
    {
        const float4* pj = &poly[5 * 9];
        #pragma unroll
        for (int f = 0; f < 9; f++) {
            float4 a = pj[f];
            Z[f] = fmaf(fmaf(fmaf(a.w, 0.5f, a.z), 0.5f, a.y), 0.5f, a.x);
        }
    }

    const float* xcol = x   + img * 4096 + lane * 2;
    float*       ocol = out + img * 4096 + lane * 2;

    float accE[3] = {0.f, 0.f, 0.f};   // even column rolling accumulators
    float accO[3] = {0.f, 0.f, 0.f};   // odd  column rolling accumulators

    auto evalf = [&](const float4* __restrict__ pj, float u, float s, int f) {
        float4 a = pj[f];
        float t = fmaf(a.w, u, a.z);
        t = fmaf(t, u, a.y);
        t = fmaf(t, u, a.x);
        return fmaf(s, bwr[f], t);
    };

    #pragma unroll
    for (int r = 0; r < NROWS; r++) {
        const int py = y0 - 1 + r;                 // pixel row
        float2 p = make_float2(0.f, 0.f);          // zero padding outside image
        if (py >= 0 && py < 64) p = *(const float2*)(xcol + py * 64);

        const float ve = p.x, vo = p.y;
        const float se = ve * __frcp_rn(1.f + __expf(-ve));
        const float so = vo * __frcp_rn(1.f + __expf(-vo));

        float xce = fmaf(ve, 2.5f, 5.5f);          // (v+2.2)/0.4
        float jfe = floorf(xce);
        float ue  = xce - jfe;
        int   je  = (int)jfe;
        if ((unsigned)je > 10u) { je = 11; ue = 0.f; }   // zero row of table

        float xco = fmaf(vo, 2.5f, 5.5f);
        float jfo = floorf(xco);
        float uo  = xco - jfo;
        int   jo  = (int)jfo;
        if ((unsigned)jo > 10u) { jo = 11; uo = 0.f; }

        const float4* pe = &poly[je * 9];
        const float4* po = &poly[jo * 9];

        // pixel col c serves out col c+1 (kw=0), c (kw=1), c-1 (kw=2);
        // pixel row py with kh serves out row py+1-kh -> slot [2-kh].
        float sendL[3], sendR[3];
        #pragma unroll
        for (int kh = 0; kh < 3; kh++) {
            accO[2 - kh] += evalf(pe, ue, se, kh * 3 + 0);  // even px -> own odd col
            accE[2 - kh] += evalf(pe, ue, se, kh * 3 + 1);  // even px -> own even col
            sendL[kh]     = evalf(pe, ue, se, kh * 3 + 2);  // even px -> lane-1 odd col
            sendR[kh]     = evalf(po, uo, so, kh * 3 + 0);  // odd  px -> lane+1 even col
            accO[2 - kh] += evalf(po, uo, so, kh * 3 + 1);
            accE[2 - kh] += evalf(po, uo, so, kh * 3 + 2);
        }

        // horizontal exchange; image-edge lanes receive the padding value Z
        #pragma unroll
        for (int kh = 0; kh < 3; kh++) {
            float rl = __shfl_down_sync(0xffffffffu, sendL[kh], 1);
            if (lane == 31) rl = Z[kh * 3 + 2];   // col 64 padding -> out col 63
            float rr = __shfl_up_sync(0xffffffffu, sendR[kh], 1);
            if (lane == 0)  rr = Z[kh * 3 + 0];   // col -1 padding -> out col 0
            accO[2 - kh] += rl;
            accE[2 - kh] += rr;
        }

        // out row py-1 complete after processing pixel row py
        if (r >= 2) {
            const int oy = y0 + r - 2;
            *(float2*)(ocol + oy * 64) = make_float2(accE[0], accO[0]);
        }
        accE[0] = accE[1]; accE[1] = accE[2]; accE[2] = 0.f;
        accO[0] = accO[1]; accO[1] = accO[2]; accO[2] = 0.f;
    }
}

extern "C" void kernel_launch(void* const* d_in, const int* in_sizes, int n_in,
                              void* d_out, int out_size) {
    const float* x  = (const float*)d_in[0];  // (8,32,64,64)
    const float* bw = (const float*)d_in[1];  // (1,9)
    const float* sw = (const float*)d_in[2];  // (1,9,8)
    const float* ss = (const float*)d_in[3];  // (1,9)
    float* out = (float*)d_out;

    // 256 images x 16 strips, 4 warp-strips per block
    kan_conv_kernel<<<1024, 128>>>(x, bw, sw, ss, out);
}

// round 7
// speedup vs baseline: 1.0226x; 1.0226x over previous
#include <cuda_runtime.h>
#include <cuda_bf16.h>
#include <cuda_fp16.h>

#define R_ROWS 8              // output rows per warp-strip
#define NROWS  (R_ROWS + 2)   // pixel rows streamed (with vertical halo)

// KAN 3x3 conv, shared KANLinear(9->1), cubic B-spline on uniform grid.
// Warp-per-strip register-rolling design; per-pixel spline polynomial
// coefficients stored as half2 pairs (8 B/feature -> LDS.64 gathers).
__global__ __launch_bounds__(32)
void kan_conv_kernel(const float* __restrict__ x,
                     const float* __restrict__ bw,
                     const float* __restrict__ sw,
                     const float* __restrict__ ss,
                     float* __restrict__ out)
{
    __shared__ uint2 polyH[12 * 9];   // [cell j][feature f] = {half2(a0,a1), half2(a2,a3)}; j=11 zero

    const int lane  = threadIdx.x;          // 0..31
    const int img   = blockIdx.x >> 3;      // 2048 blocks = 256 images x 8 strips
    const int strip = blockIdx.x & 7;
    const int y0    = strip * R_ROWS;

    // ---- build polynomial table (scaled spline weights -> cubic coeffs, fp16) ----
    // Uniform cubic B-spline bases contracted with padded weights W[c]:
    //   a0=(W0+4W1+W2)/6, a1=(W2-W0)/2, a2=(W0-2W1+W2)/2, a3=(W3-W0+3(W1-W2))/6
    for (int t = lane; t < 108; t += 32) {
        int j = t / 9, f = t - j * 9;
        float a0 = 0.f, a1 = 0.f, a2 = 0.f, a3 = 0.f;
        if (j < 11) {
            float scale = __ldg(&ss[f]);
            float W[4];
            #pragma unroll
            for (int c = 0; c < 4; c++) {
                int bi = j + c - 3;
                W[c] = (bi >= 0 && bi < 8) ? __ldg(&sw[f * 8 + bi]) * scale : 0.f;
            }
            const float S = 1.f / 6.f;
            a0 = (W[0] + 4.f * W[1] + W[2]) * S;
            a1 = (W[2] - W[0]) * 0.5f;
            a2 = (W[0] - 2.f * W[1] + W[2]) * 0.5f;
            a3 = (W[3] - W[0] + 3.f * (W[1] - W[2])) * S;
        }
        __half2 h01 = __floats2half2_rn(a0, a1);
        __half2 h23 = __floats2half2_rn(a2, a3);
        uint2 e;
        e.x = *reinterpret_cast<unsigned*>(&h01);
        e.y = *reinterpret_cast<unsigned*>(&h23);
        polyH[t] = e;
    }
    float bwr[9];
    #pragma unroll
    for (int f = 0; f < 9; f++) bwr[f] = __ldg(&bw[f]);
    __syncthreads();

    // ---- spline value at x = 0 (padding pixels): cell j=5, u=0.5, fp32 exact ----
    float Z[9];
    #pragma unroll
    for (int f = 0; f < 9; f++) {
        float scale = __ldg(&ss[f]);
        float W0 = __ldg(&sw[f * 8 + 2]) * scale;
        float W1 = __ldg(&sw[f * 8 + 3]) * scale;
        float W2 = __ldg(&sw[f * 8 + 4]) * scale;
        float W3 = __ldg(&sw[f * 8 + 5]) * scale;
        const float S = 1.f / 6.f;
        float a0 = (W0 + 4.f * W1 + W2) * S;
        float a1 = (W2 - W0) * 0.5f;
        float a2 = (W0 - 2.f * W1 + W2) * 0.5f;
        float a3 = (W3 - W0 + 3.f * (W1 - W2)) * S;
        Z[f] = fmaf(fmaf(fmaf(a3, 0.5f, a2), 0.5f, a1), 0.5f, a0);
    }

    const float* xcol = x   + img * 4096 + lane * 2;
    float*       ocol = out + img * 4096 + lane * 2;

    float accE[3] = {0.f, 0.f, 0.f};   // even column rolling accumulators
    float accO[3] = {0.f, 0.f, 0.f};   // odd  column rolling accumulators

    // v[f] = silu*bw[f] + cubic(u); coefficients gathered as one LDS.64
    auto evalf = [&](int jbase, float u, float s, int f) {
        uint2 pk = polyH[jbase + f];
        float2 c01 = __half22float2(*reinterpret_cast<__half2*>(&pk.x));
        float2 c23 = __half22float2(*reinterpret_cast<__half2*>(&pk.y));
        float t = fmaf(c23.y, u, c23.x);
        t = fmaf(t, u, c01.y);
        t = fmaf(t, u, c01.x);
        return fmaf(s, bwr[f], t);
    };

    #pragma unroll
    for (int r = 0; r < NROWS; r++) {
        const int py = y0 - 1 + r;                 // pixel row
        float2 p = make_float2(0.f, 0.f);          // zero padding outside image
        if (py >= 0 && py < 64) p = *(const float2*)(xcol + py * 64);

        const float ve = p.x, vo = p.y;
        const float se = ve * __frcp_rn(1.f + __expf(-ve));
        const float so = vo * __frcp_rn(1.f + __expf(-vo));

        float xce = fmaf(ve, 2.5f, 5.5f);          // (v+2.2)/0.4
        float jfe = floorf(xce);
        float ue  = xce - jfe;
        int   je  = (int)jfe;
        if ((unsigned)je > 10u) { je = 11; ue = 0.f; }   // zero row of table

        float xco = fmaf(vo, 2.5f, 5.5f);
        float jfo = floorf(xco);
        float uo  = xco - jfo;
        int   jo  = (int)jfo;
        if ((unsigned)jo > 10u) { jo = 11; uo = 0.f; }

        const int jbe = je * 9;
        const int jbo = jo * 9;

        // pixel col c serves out col c+1 (kw=0), c (kw=1), c-1 (kw=2);
        // pixel row py with kh serves out row py+1-kh -> slot [2-kh].
        float sendL[3], sendR[3];
        #pragma unroll
        for (int kh = 0; kh < 3; kh++) {
            accO[2 - kh] += evalf(jbe, ue, se, kh * 3 + 0);  // even px -> own odd col
            accE[2 - kh] += evalf(jbe, ue, se, kh * 3 + 1);  // even px -> own even col
            sendL[kh]     = evalf(jbe, ue, se, kh * 3 + 2);  // even px -> lane-1 odd col
            sendR[kh]     = evalf(jbo, uo, so, kh * 3 + 0);  // odd  px -> lane+1 even col
            accO[2 - kh] += evalf(jbo, uo, so, kh * 3 + 1);
            accE[2 - kh] += evalf(jbo, uo, so, kh * 3 + 2);
        }

        // horizontal exchange; image-edge lanes receive the padding value Z
        #pragma unroll
        for (int kh = 0; kh < 3; kh++) {
            float rl = __shfl_down_sync(0xffffffffu, sendL[kh], 1);
            if (lane == 31) rl = Z[kh * 3 + 2];   // col 64 padding -> out col 63
            float rr = __shfl_up_sync(0xffffffffu, sendR[kh], 1);
            if (lane == 0)  rr = Z[kh * 3 + 0];   // col -1 padding -> out col 0
            accO[2 - kh] += rl;
            accE[2 - kh] += rr;
        }

        // out row py-1 complete after processing pixel row py
        if (r >= 2) {
            const int oy = y0 + r - 2;
            *(float2*)(ocol + oy * 64) = make_float2(accE[0], accO[0]);
        }
        accE[0] = accE[1]; accE[1] = accE[2]; accE[2] = 0.f;
        accO[0] = accO[1]; accO[1] = accO[2]; accO[2] = 0.f;
    }
}

extern "C" void kernel_launch(void* const* d_in, const int* in_sizes, int n_in,
                              void* d_out, int out_size) {
    const float* x  = (const float*)d_in[0];  // (8,32,64,64)
    const float* bw = (const float*)d_in[1];  // (1,9)
    const float* sw = (const float*)d_in[2];  // (1,9,8)
    const float* ss = (const float*)d_in[3];  // (1,9)
    float* out = (float*)d_out;

    // 256 images x 8 strips, one warp per strip
    kan_conv_kernel<<<2048, 32>>>(x, bw, sw, ss, out);
}

// round 8
// speedup vs baseline: 1.2179x; 1.1910x over previous
#include <cuda_runtime.h>
#include <cuda_bf16.h>
#include <cuda_fp16.h>

#define R_ROWS 4              // output rows per warp-strip
#define NROWS  (R_ROWS + 2)   // pixel rows streamed (with vertical halo)

// KAN 3x3 conv, shared KANLinear(9->1), cubic B-spline on uniform grid.
// Warp-per-strip register-rolling design, R=4 for occupancy, fp16 coeff table:
//  - lane l owns output columns (2l, 2l+1); warp covers the full 64-wide row.
//  - per pixel: v[f] = silu(x)*bw[f] + cubic_{f,cell(x)}(u), accumulated into
//    3 rolling row accumulators; horizontal exchange = 6 shuffles per row.
//  - coefficients stored as half2 pairs (8 B/feature -> LDS.64 gathers),
//    Horner in fp32.
//  - 4 warps/block share the table build; padding constants Z in smem.
__global__ __launch_bounds__(128, 7)
void kan_conv_kernel(const float* __restrict__ x,
                     const float* __restrict__ bw,
                     const float* __restrict__ sw,
                     const float* __restrict__ ss,
                     float* __restrict__ out)
{
    __shared__ uint2 polyH[12 * 9];   // [cell j][feature f] = {h2(a0,a1), h2(a2,a3)}; j=11 zero
    __shared__ float Zs[9];           // spline value at padding pixels (x=0)

    const int lane  = threadIdx.x & 31;
    const int warp  = threadIdx.x >> 5;
    const int img   = blockIdx.x >> 2;                  // 1024 blocks = 256 images x 4
    const int strip = ((blockIdx.x & 3) << 2) | warp;   // 0..15
    const int y0    = strip * R_ROWS;

    // ---- build polynomial table once per block ----
    // Uniform cubic B-spline bases contracted with padded weights W[c]:
    //   a0=(W0+4W1+W2)/6, a1=(W2-W0)/2, a2=(W0-2W1+W2)/2, a3=(W3-W0+3(W1-W2))/6
    if (threadIdx.x < 108) {
        const int t = threadIdx.x;
        const int j = t / 9, f = t - j * 9;
        float a0 = 0.f, a1 = 0.f, a2 = 0.f, a3 = 0.f;
        if (j < 11) {
            float scale = __ldg(&ss[f]);
            float W[4];
            #pragma unroll
            for (int c = 0; c < 4; c++) {
                int bi = j + c - 3;
                W[c] = (bi >= 0 && bi < 8) ? __ldg(&sw[f * 8 + bi]) * scale : 0.f;
            }
            const float S = 1.f / 6.f;
            a0 = (W[0] + 4.f * W[1] + W[2]) * S;
            a1 = (W[2] - W[0]) * 0.5f;
            a2 = (W[0] - 2.f * W[1] + W[2]) * 0.5f;
            a3 = (W[3] - W[0] + 3.f * (W[1] - W[2])) * S;
        }
        __half2 h01 = __floats2half2_rn(a0, a1);
        __half2 h23 = __floats2half2_rn(a2, a3);
        uint2 e;
        e.x = *reinterpret_cast<unsigned*>(&h01);
        e.y = *reinterpret_cast<unsigned*>(&h23);
        polyH[t] = e;
        // padding value: x=0 -> cell j=5, u=0.5, silu=0 (fp32 exact)
        if (j == 5) Zs[f] = fmaf(fmaf(fmaf(a3, 0.5f, a2), 0.5f, a1), 0.5f, a0);
    }
    float bwr[9];
    #pragma unroll
    for (int f = 0; f < 9; f++) bwr[f] = __ldg(&bw[f]);
    __syncthreads();

    float Z[9];
    #pragma unroll
    for (int f = 0; f < 9; f++) Z[f] = Zs[f];

    const float* xcol = x   + img * 4096 + lane * 2;
    float*       ocol = out + img * 4096 + lane * 2;

    float accE[3] = {0.f, 0.f, 0.f};   // even column rolling accumulators
    float accO[3] = {0.f, 0.f, 0.f};   // odd  column rolling accumulators

    // v[f] = silu*bw[f] + cubic(u); coefficients gathered as one LDS.64
    auto evalf = [&](int jbase, float u, float s, int f) {
        uint2 pk = polyH[jbase + f];
        float2 c01 = __half22float2(*reinterpret_cast<__half2*>(&pk.x));
        float2 c23 = __half22float2(*reinterpret_cast<__half2*>(&pk.y));
        float t = fmaf(c23.y, u, c23.x);
        t = fmaf(t, u, c01.y);
        t = fmaf(t, u, c01.x);
        return fmaf(s, bwr[f], t);
    };

    #pragma unroll
    for (int r = 0; r < NROWS; r++) {
        const int py = y0 - 1 + r;                 // pixel row
        float2 p = make_float2(0.f, 0.f);          // zero padding outside image
        if (py >= 0 && py < 64) p = *(const float2*)(xcol + py * 64);

        const float ve = p.x, vo = p.y;
        const float se = ve * __frcp_rn(1.f + __expf(-ve));
        const float so = vo * __frcp_rn(1.f + __expf(-vo));

        float xce = fmaf(ve, 2.5f, 5.5f);          // (v+2.2)/0.4
        float jfe = floorf(xce);
        float ue  = xce - jfe;
        int   je  = (int)jfe;
        if ((unsigned)je > 10u) { je = 11; ue = 0.f; }   // zero row of table

        float xco = fmaf(vo, 2.5f, 5.5f);
        float jfo = floorf(xco);
        float uo  = xco - jfo;
        int   jo  = (int)jfo;
        if ((unsigned)jo > 10u) { jo = 11; uo = 0.f; }

        const int jbe = je * 9;
        const int jbo = jo * 9;

        // pixel col c serves out col c+1 (kw=0), c (kw=1), c-1 (kw=2);
        // pixel row py with kh serves out row py+1-kh -> slot [2-kh].
        float sendL[3], sendR[3];
        #pragma unroll
        for (int kh = 0; kh < 3; kh++) {
            accO[2 - kh] += evalf(jbe, ue, se, kh * 3 + 0);  // even px -> own odd col
            accE[2 - kh] += evalf(jbe, ue, se, kh * 3 + 1);  // even px -> own even col
            sendL[kh]     = evalf(jbe, ue, se, kh * 3 + 2);  // even px -> lane-1 odd col
            sendR[kh]     = evalf(jbo, uo, so, kh * 3 + 0);  // odd  px -> lane+1 even col
            accO[2 - kh] += evalf(jbo, uo, so, kh * 3 + 1);
            accE[2 - kh] += evalf(jbo, uo, so, kh * 3 + 2);
        }

        // horizontal exchange; image-edge lanes receive the padding value Z
        #pragma unroll
        for (int kh = 0; kh < 3; kh++) {
            float rl = __shfl_down_sync(0xffffffffu, sendL[kh], 1);
            if (lane == 31) rl = Z[kh * 3 + 2];   // col 64 padding -> out col 63
            float rr = __shfl_up_sync(0xffffffffu, sendR[kh], 1);
            if (lane == 0)  rr = Z[kh * 3 + 0];   // col -1 padding -> out col 0
            accO[2 - kh] += rl;
            accE[2 - kh] += rr;
        }

        // out row py-1 complete after processing pixel row py
        if (r >= 2) {
            const int oy = y0 + r - 2;
            *(float2*)(ocol + oy * 64) = make_float2(accE[0], accO[0]);
        }
        accE[0] = accE[1]; accE[1] = accE[2]; accE[2] = 0.f;
        accO[0] = accO[1]; accO[1] = accO[2]; accO[2] = 0.f;
    }
}

extern "C" void kernel_launch(void* const* d_in, const int* in_sizes, int n_in,
                              void* d_out, int out_size) {
    const float* x  = (const float*)d_in[0];  // (8,32,64,64)
    const float* bw = (const float*)d_in[1];  // (1,9)
    const float* sw = (const float*)d_in[2];  // (1,9,8)
    const float* ss = (const float*)d_in[3];  // (1,9)
    float* out = (float*)d_out;

    // 256 images x 16 strips, 4 warp-strips per block
    kan_conv_kernel<<<1024, 128>>>(x, bw, sw, ss, out);
}